// round 4
// baseline (speedup 1.0000x reference)
#include <cuda_runtime.h>

// Problem constants (fixed by the reference: N=16384, D=2, H=128)
constexpr int N_ROWS = 16384;
constexpr int H      = 128;
constexpr int NHi    = N_ROWS * H;          // floats per [N,H] tensor

// K1: streaming pass
constexpr int BLOCKS1  = 1024;
constexpr int THREADS  = 256;
constexpr int WPB      = 8;                              // warps per block
constexpr int TW1      = BLOCKS1 * WPB;                  // 8192 warps
constexpr int RPW1     = N_ROWS / TW1;                   // 2 rows/warp

// K2: nce pass
constexpr int BLOCKS2  = 512;
constexpr int TW2      = BLOCKS2 * WPB;                  // 4096 warps
constexpr int RPW2     = N_ROWS / TW2;                   // 4 rows/warp

// Persistent scratch (allocation-free __device__ globals). Zero at module
// load; K2's last block re-zeros everything so each graph replay starts clean.
__device__ float    g_h[N_ROWS];     // per-row: sum_cols(-N*e^2 + 10*(e-f)^2)
__device__ float    g_ysum[H];       // sum_y bi_dec[y][c]
__device__ float    g_scalars[3];    // [0]=Synorm  [1]=sum diag  [2]=nce
__device__ unsigned g_ticket;        // last-block election in K2

__device__ __forceinline__ float warp_sum(float v) {
    #pragma unroll
    for (int o = 16; o > 0; o >>= 1) v += __shfl_down_sync(0xffffffffu, v, o);
    return v;
}

// K1: single streaming pass over enc+dec (33.5 MB in, 25.2 MB out).
// No grid barrier -> blocks retire independently, waves schedule freely.
__global__ __launch_bounds__(THREADS) void stream_kernel(
    const float* __restrict__ enc, const float* __restrict__ dec,
    float* __restrict__ out)
{
    const int tid   = threadIdx.x;
    const int lane  = tid & 31;
    const int w     = tid >> 5;
    const int gwarp = blockIdx.x * WPB + w;

    float ys0 = 0.f, ys1 = 0.f, ys2 = 0.f, ys3 = 0.f;
    float ynorm = 0.f, dgsum = 0.f;

    #pragma unroll
    for (int i = 0; i < RPW1; i++) {
        const int r = gwarp + i * TW1;
        // row r = 256 floats = 64 float4; direction halves at +0 / +32
        const float4 a = __ldg((const float4*)enc + r * 64 + lane);
        const float4 b = __ldg((const float4*)enc + r * 64 + 32 + lane);
        const float4 c = __ldg((const float4*)dec + r * 64 + lane);
        const float4 d = __ldg((const float4*)dec + r * 64 + 32 + lane);

        float4 e; e.x = a.x + b.x; e.y = a.y + b.y; e.z = a.z + b.z; e.w = a.w + b.w;
        float4 f; f.x = c.x + d.x; f.y = c.y + d.y; f.z = c.z + d.z; f.w = c.w + d.w;

        ((float4*)out)[          r * 32 + lane] = e;   // bi_enc
        ((float4*)out)[NHi / 4 + r * 32 + lane] = e;   // bi_enc (again)
        ((float4*)out)[NHi / 2 + r * 32 + lane] = f;   // bi_dec

        ys0 += f.x; ys1 += f.y; ys2 += f.z; ys3 += f.w;
        ynorm += f.x * f.x + f.y * f.y + f.z * f.z + f.w * f.w;

        const float en  = e.x * e.x + e.y * e.y + e.z * e.z + e.w * e.w;
        const float gx = e.x - f.x, gy = e.y - f.y, gz = e.z - f.z, gw = e.w - f.w;
        const float dgl = gx * gx + gy * gy + gz * gz + gw * gw;

        dgsum += dgl;
        float h = warp_sum(fmaf(-(float)N_ROWS, en, 10.0f * dgl));
        if (lane == 0) g_h[r] = h;          // 64 KB side array
    }
    ynorm = warp_sum(ynorm);
    dgsum = warp_sum(dgsum);

    __shared__ float s_ys[WPB][H];
    __shared__ float s_sc[WPB][2];
    s_ys[w][4 * lane + 0] = ys0;
    s_ys[w][4 * lane + 1] = ys1;
    s_ys[w][4 * lane + 2] = ys2;
    s_ys[w][4 * lane + 3] = ys3;
    if (lane == 0) { s_sc[w][0] = ynorm; s_sc[w][1] = dgsum; }
    __syncthreads();

    if (tid < H) {
        float s = 0.f;
        #pragma unroll
        for (int ww = 0; ww < WPB; ww++) s += s_ys[ww][tid];
        atomicAdd(&g_ysum[tid], s);
    } else if (tid == H) {
        float yn = 0.f, ds = 0.f;
        #pragma unroll
        for (int ww = 0; ww < WPB; ww++) { yn += s_sc[ww][0]; ds += s_sc[ww][1]; }
        atomicAdd(&g_scalars[0], yn);
        atomicAdd(&g_scalars[1], ds);
    }
}

// K2: nce from L2-resident bi_enc + g_h. Last-arriving block (atomic ticket)
// writes the two scalar outputs and re-zeros all persistent state.
__global__ __launch_bounds__(THREADS) void nce_kernel(float* __restrict__ out)
{
    const int tid   = threadIdx.x;
    const int lane  = tid & 31;
    const int w     = tid >> 5;
    const int gwarp = blockIdx.x * WPB + w;

    const float4 ys = ((const float4*)g_ysum)[lane];
    const float synorm = g_scalars[0];

    float acc = 0.f;
    #pragma unroll
    for (int i = 0; i < RPW2; i++) {
        const int r = gwarp + i * TW2;
        const float4 e = __ldg((const float4*)out + r * 32 + lane);   // bi_enc, L2
        float dp = e.x * ys.x + e.y * ys.y + e.z * ys.z + e.w * ys.w;
        dp = warp_sum(dp);
        if (lane == 0)
            acc += fmaxf(5.0f - synorm + fmaf(2.0f, dp, g_h[r]), 0.0f);
    }

    __shared__ float s_nce[WPB];
    if (lane == 0) s_nce[w] = acc;
    __syncthreads();

    if (tid == 0) {
        float tn = 0.f;
        #pragma unroll
        for (int ww = 0; ww < WPB; ww++) tn += s_nce[ww];
        atomicAdd(&g_scalars[2], tn);
        __threadfence();
        const unsigned t = atomicAdd(&g_ticket, 1u);
        if (t == BLOCKS2 - 1) {
            // All blocks' nce partials are visible (their fences precede
            // their ticket increments, and we observed all tickets).
            const float nce  = atomicAdd(&g_scalars[2], 0.0f);
            const float diag = g_scalars[1];
            out[3 * NHi]     = nce;                        // nce_loss
            out[3 * NHi + 1] = -diag / (float)N_ROWS;      // diagonal_loss
            // Re-zero persistent state for the next graph replay.
            #pragma unroll
            for (int i = 0; i < H; i++) g_ysum[i] = 0.0f;
            g_scalars[0] = 0.0f; g_scalars[1] = 0.0f; g_scalars[2] = 0.0f;
            atomicExch(&g_ticket, 0u);
        }
    }
}

extern "C" void kernel_launch(void* const* d_in, const int* in_sizes, int n_in,
                              void* d_out, int out_size) {
    const float* enc = (const float*)d_in[0];
    const float* dec = (const float*)d_in[1];
    float* out = (float*)d_out;

    stream_kernel<<<BLOCKS1, THREADS>>>(enc, dec, out);
    nce_kernel<<<BLOCKS2, THREADS>>>(out);
}

// round 5
// speedup vs baseline: 1.0152x; 1.0152x over previous
#include <cuda_runtime.h>

// Problem constants (fixed by the reference: N=16384, D=2, H=128)
constexpr int N_ROWS = 16384;
constexpr int H      = 128;
constexpr int NHi    = N_ROWS * H;          // floats per [N,H] tensor

constexpr int BLOCKS  = 512;
constexpr int THREADS = 256;
constexpr int WPB     = 8;                           // warps per block
constexpr int TW      = BLOCKS * WPB;                // 4096 warps
constexpr int RPW     = N_ROWS / TW;                 // 4 rows per warp

// Persistent scratch (allocation-free __device__ globals). Zero at load;
// the ticket-elected last block re-zeros at the end of every run.
__device__ float    g_ysum[H];      // sum_y bi_dec[y][c]
__device__ float    g_scalars[3];   // [0]=Synorm  [1]=sum diag  [2]=nce
__device__ unsigned g_count;        // barrier arrivals (returns to 0)
__device__ unsigned g_gen;          // barrier generation (monotonic)
__device__ unsigned g_ticket;       // last-block election

__device__ __forceinline__ float warp_sum(float v) {
    #pragma unroll
    for (int o = 16; o > 0; o >>= 1) v += __shfl_down_sync(0xffffffffu, v, o);
    return v;
}

// Software grid barrier; all 512 blocks co-resident (512 <= 4/SM * 148 SMs,
// guaranteed by __launch_bounds__(256, 4)).
__device__ __forceinline__ void grid_barrier() {
    __syncthreads();
    if (threadIdx.x == 0) {
        __threadfence();
        volatile unsigned* genp = &g_gen;
        const unsigned gen = *genp;                  // read BEFORE arriving
        if (atomicAdd(&g_count, 1u) == BLOCKS - 1) {
            atomicExch(&g_count, 0u);
            __threadfence();
            atomicAdd(&g_gen, 1u);                   // release
        } else {
            while (*genp == gen) { __nanosleep(32); }
        }
        __threadfence();
    }
    __syncthreads();
}

__global__ __launch_bounds__(THREADS, 4) void fused_kernel(
    const float* __restrict__ enc, const float* __restrict__ dec,
    float* __restrict__ out)
{
    const int tid   = threadIdx.x;
    const int lane  = tid & 31;
    const int w     = tid >> 5;
    const int gwarp = blockIdx.x * WPB + w;

    __shared__ float s_ys[WPB][H];
    __shared__ float s_sc[WPB][2];

    // ---------- Phase 1 (dec only, 25.2 MB): bi_dec + Ysum + Synorm ----------
    float4 f_reg[RPW];                 // bi_dec kept in registers across barrier
    float ys0 = 0.f, ys1 = 0.f, ys2 = 0.f, ys3 = 0.f;
    float ynorm = 0.f;

    #pragma unroll
    for (int i = 0; i < RPW; i++) {
        const int r = gwarp + i * TW;
        const float4 c = __ldg((const float4*)dec + r * 64 + lane);
        const float4 d = __ldg((const float4*)dec + r * 64 + 32 + lane);
        float4 f; f.x = c.x + d.x; f.y = c.y + d.y; f.z = c.z + d.z; f.w = c.w + d.w;

        ((float4*)out)[NHi / 2 + r * 32 + lane] = f;   // bi_dec output

        ys0 += f.x; ys1 += f.y; ys2 += f.z; ys3 += f.w;
        ynorm += f.x * f.x + f.y * f.y + f.z * f.z + f.w * f.w;
        f_reg[i] = f;
    }
    ynorm = warp_sum(ynorm);

    s_ys[w][4 * lane + 0] = ys0;
    s_ys[w][4 * lane + 1] = ys1;
    s_ys[w][4 * lane + 2] = ys2;
    s_ys[w][4 * lane + 3] = ys3;
    if (lane == 0) s_sc[w][0] = ynorm;
    __syncthreads();

    if (tid < H) {
        float s = 0.f;
        #pragma unroll
        for (int ww = 0; ww < WPB; ww++) s += s_ys[ww][tid];
        atomicAdd(&g_ysum[tid], s);
    } else if (tid == H) {
        float yn = 0.f;
        #pragma unroll
        for (int ww = 0; ww < WPB; ww++) yn += s_sc[ww][0];
        atomicAdd(&g_scalars[0], yn);
    }

    grid_barrier();   // Ysum / Synorm complete; only 25 MB of work gated here

    // ---------- Phase 2 (enc, 33.6 MB): bi_enc x2 + diag + nce ----------
    const float4 ys = __ldcg((const float4*)g_ysum + lane);   // L2-fresh
    const float synorm = __ldcg(&g_scalars[0]);

    float dg_acc = 0.f, nce_acc = 0.f;

    #pragma unroll
    for (int i = 0; i < RPW; i++) {
        const int r = gwarp + i * TW;
        const float4 a = __ldg((const float4*)enc + r * 64 + lane);
        const float4 b = __ldg((const float4*)enc + r * 64 + 32 + lane);
        float4 e; e.x = a.x + b.x; e.y = a.y + b.y; e.z = a.z + b.z; e.w = a.w + b.w;

        ((float4*)out)[          r * 32 + lane] = e;   // bi_enc
        ((float4*)out)[NHi / 4 + r * 32 + lane] = e;   // bi_enc (again)

        const float4 f = f_reg[i];
        const float gx = e.x - f.x, gy = e.y - f.y, gz = e.z - f.z, gw = e.w - f.w;
        const float dgl = gx * gx + gy * gy + gz * gz + gw * gw;
        const float en  = e.x * e.x + e.y * e.y + e.z * e.z + e.w * e.w;
        const float dp  = e.x * ys.x + e.y * ys.y + e.z * ys.z + e.w * ys.w;

        dg_acc += dgl;
        float q = fmaf(-(float)N_ROWS, en, fmaf(2.0f, dp, 10.0f * dgl));
        q = warp_sum(q);
        if (lane == 0) nce_acc += fmaxf(5.0f - synorm + q, 0.0f);
    }
    dg_acc = warp_sum(dg_acc);

    if (lane == 0) { s_sc[w][0] = nce_acc; s_sc[w][1] = dg_acc; }
    __syncthreads();

    if (tid == 0) {
        float tn = 0.f, td = 0.f;
        #pragma unroll
        for (int ww = 0; ww < WPB; ww++) { tn += s_sc[ww][0]; td += s_sc[ww][1]; }
        atomicAdd(&g_scalars[2], tn);
        atomicAdd(&g_scalars[1], td);
        __threadfence();
        // Last-arriving block writes scalars and re-zeros persistent state.
        if (atomicAdd(&g_ticket, 1u) == BLOCKS - 1) {
            const float nce  = atomicAdd(&g_scalars[2], 0.0f);
            const float diag = atomicAdd(&g_scalars[1], 0.0f);
            out[3 * NHi]     = nce;                        // nce_loss
            out[3 * NHi + 1] = -diag / (float)N_ROWS;      // diagonal_loss
            #pragma unroll
            for (int i = 0; i < H; i++) g_ysum[i] = 0.0f;
            g_scalars[0] = 0.0f; g_scalars[1] = 0.0f; g_scalars[2] = 0.0f;
            atomicExch(&g_ticket, 0u);
        }
    }
}

extern "C" void kernel_launch(void* const* d_in, const int* in_sizes, int n_in,
                              void* d_out, int out_size) {
    const float* enc = (const float*)d_in[0];
    const float* dec = (const float*)d_in[1];
    float* out = (float*)d_out;

    fused_kernel<<<BLOCKS, THREADS>>>(enc, dec, out);
}